// round 14
// baseline (speedup 1.0000x reference)
#include <cuda_runtime.h>
#include <cuda_bf16.h>
#include <math.h>
#include <stdint.h>

#define NN 50000
#define EE 800000
#define DIN 128
#define DH 256
#define SCAN_B 49  // ceil(NN/1024)

typedef __nv_bfloat16 bf16;
typedef __nv_bfloat162 bf162;

// ---------------- scratch (static device globals; no allocations) -----------
__device__ __align__(16) float g_h[NN * DH];
__device__ __align__(16) float g_m[NN * DH];
__device__ __align__(16) float g_res[NN * DH];
__device__ __align__(16) bf16  g_p1h[NN * DH];
__device__ __align__(16) bf16  g_p1l[NN * DH];
__device__ __align__(16) bf16  g_p2h[NN * DH];
__device__ __align__(16) bf16  g_p2l[NN * DH];
__device__ __align__(16) bf16  g_wh[6 * DH * DH];  // transposed [N][K] hi planes
__device__ __align__(16) bf16  g_wl[6 * DH * DH];
__device__ __align__(16) int   g_cnt[NN];
__device__ __align__(16) int   g_off[NN + 1];
__device__ __align__(16) int   g_cursor[NN];
__device__ __align__(16) int   g_csr[EE];
__device__ __align__(16) int   g_bsum[64];
__device__ __align__(16) int   g_bbase[64];
__device__ __align__(16) float g_isd[NN];
__device__ __align__(16) float g_id[NN];
__device__ __align__(16) double g_stats[2 * DH];

// ---------------- helpers ---------------------------------------------------
__device__ __forceinline__ float gelu_tanh(float x) {
    float x3 = x * x * x;
    return 0.5f * x * (1.0f + tanhf(0.7978845608028654f * (x + 0.044715f * x3)));
}

__device__ __forceinline__ void bsplit(float x, bf16& h, bf16& l) {
    h = __float2bfloat16_rn(x);
    l = __float2bfloat16_rn(x - __bfloat162float(h));
}

__device__ __forceinline__ uint32_t smem_u32(const void* p) {
    uint32_t a;
    asm("{ .reg .u64 t; cvta.to.shared.u64 t, %1; cvt.u32.u64 %0, t; }" : "=r"(a) : "l"(p));
    return a;
}

__device__ __forceinline__ void mma_bf16(float& c0, float& c1, float& c2, float& c3,
                                         unsigned a0, unsigned a1, unsigned a2, unsigned a3,
                                         unsigned b0, unsigned b1) {
    asm volatile("mma.sync.aligned.m16n8k16.row.col.f32.bf16.bf16.f32 "
                 "{%0,%1,%2,%3},{%4,%5,%6,%7},{%8,%9},{%0,%1,%2,%3};"
                 : "+f"(c0), "+f"(c1), "+f"(c2), "+f"(c3)
                 : "r"(a0), "r"(a1), "r"(a2), "r"(a3), "r"(b0), "r"(b1));
}

__device__ __forceinline__ void cpa16(uint32_t d, const void* s, int srcsz) {
    asm volatile("cp.async.ca.shared.global [%0], [%1], 16, %2;"
                 :: "r"(d), "l"(s), "r"(srcsz) : "memory");
}

#define LDSM4(r0, r1, r2, r3, addr)                                            \
    asm volatile("ldmatrix.sync.aligned.m8n8.x4.shared.b16 {%0,%1,%2,%3}, [%4];" \
                 : "=r"(r0), "=r"(r1), "=r"(r2), "=r"(r3) : "r"(addr))
#define LDSM2(r0, r1, addr)                                                    \
    asm volatile("ldmatrix.sync.aligned.m8n8.x2.shared.b16 {%0,%1}, [%2];"     \
                 : "=r"(r0), "=r"(r1) : "r"(addr))

// ---------------- degree + CSR ----------------------------------------------
__global__ void k_zero_cnt() {
    int i = blockIdx.x * blockDim.x + threadIdx.x;
    if (i < NN) g_cnt[i] = 0;
}

__global__ void k_deg_count(const int* __restrict__ dst) {
    int e = blockIdx.x * blockDim.x + threadIdx.x;
    if (e < EE) atomicAdd(&g_cnt[dst[e]], 1);
}

__global__ void k_deg_final() {
    int i = blockIdx.x * blockDim.x + threadIdx.x;
    if (i < NN) {
        float d = (float)g_cnt[i] + 1.0f;
        g_isd[i] = rsqrtf(d);
        g_id[i] = 1.0f / d;
    }
}

__global__ void k_scan1() {
    __shared__ int sm[1024];
    int tid = threadIdx.x;
    int i = blockIdx.x * 1024 + tid;
    int v = (i < NN) ? g_cnt[i] : 0;
    sm[tid] = v;
    __syncthreads();
#pragma unroll
    for (int off = 1; off < 1024; off <<= 1) {
        int t = (tid >= off) ? sm[tid - off] : 0;
        __syncthreads();
        sm[tid] += t;
        __syncthreads();
    }
    if (i < NN) g_off[i + 1] = sm[tid];
    if (tid == 1023) g_bsum[blockIdx.x] = sm[1023];
}

__global__ void k_scan2() {
    __shared__ int sm[64];
    int tid = threadIdx.x;
    int v = (tid < SCAN_B) ? g_bsum[tid] : 0;
    sm[tid] = v;
    __syncthreads();
#pragma unroll
    for (int off = 1; off < 64; off <<= 1) {
        int t = (tid >= off) ? sm[tid - off] : 0;
        __syncthreads();
        sm[tid] += t;
        __syncthreads();
    }
    if (tid < SCAN_B) g_bbase[tid] = sm[tid] - v;
}

__global__ void k_scan3() {
    int i = blockIdx.x * 1024 + threadIdx.x;
    if (i < NN) {
        int incl = g_off[i + 1] + g_bbase[blockIdx.x];
        g_off[i + 1] = incl;
        g_cursor[i] = incl - g_cnt[i];
    }
    if (i == 0) g_off[0] = 0;
}

__global__ void k_csr_fill(const int* __restrict__ src, const int* __restrict__ dst) {
    int e = blockIdx.x * blockDim.x + threadIdx.x;
    if (e < EE) {
        int p = atomicAdd(&g_cursor[dst[e]], 1);
        g_csr[p] = src[e];
    }
}

// ---------------- splitting producers ---------------------------------------
__global__ void k_split_x(const float* __restrict__ x, bf16* __restrict__ oh,
                          bf16* __restrict__ ol) {
    int idx = blockIdx.x * blockDim.x + threadIdx.x;  // float4 index
    if (idx >= NN * (DIN / 4)) return;
    float4 v = ((const float4*)x)[idx];
    bf16 h0, l0, h1, l1, h2, l2, h3, l3;
    bsplit(v.x, h0, l0); bsplit(v.y, h1, l1);
    bsplit(v.z, h2, l2); bsplit(v.w, h3, l3);
    ((bf162*)oh)[idx * 2 + 0] = bf162{h0, h1};
    ((bf162*)oh)[idx * 2 + 1] = bf162{h2, h3};
    ((bf162*)ol)[idx * 2 + 0] = bf162{l0, l1};
    ((bf162*)ol)[idx * 2 + 1] = bf162{l2, l3};
}

__global__ void k_split_w(const float* __restrict__ W, int K,
                          bf16* __restrict__ oh, bf16* __restrict__ ol) {
    int idx = blockIdx.x * blockDim.x + threadIdx.x;
    if (idx >= K * DH) return;
    int k = idx / DH, n = idx % DH;
    bf16 h, l;
    bsplit(W[idx], h, l);
    oh[n * K + k] = h;
    ol[n * K + k] = l;
}

__global__ void k_zero_out(float* __restrict__ out) {
    int i = blockIdx.x * blockDim.x + threadIdx.x;
    if (i < NN) out[i] = 0.0f;
}

__global__ void k_mask_out(float* __restrict__ out, const int* __restrict__ mask,
                           const float* __restrict__ hb) {
    int i = blockIdx.x * blockDim.x + threadIdx.x;
    if (i < NN) out[i] = (mask[i] != 0) ? (out[i] + __ldg(&hb[0])) : 0.0f;
}

// ---------------- aggregation: warp-per-node CSR gather -> planes -----------
template <int D>
__global__ void k_gather(const float* __restrict__ h, bf16* __restrict__ oh,
                         bf16* __restrict__ ol) {
    int w = (blockIdx.x * blockDim.x + threadIdx.x) >> 5;
    int lane = threadIdx.x & 31;
    if (w >= NN) return;
    const int NF = D / 128;
    const float4* hn = (const float4*)(h + (size_t)w * D);
    float idg = g_id[w], isdd = g_isd[w];
    float4 acc[NF];
#pragma unroll
    for (int t = 0; t < NF; t++) {
        float4 v = hn[lane + 32 * t];
        acc[t] = make_float4(v.x * idg, v.y * idg, v.z * idg, v.w * idg);
    }
    int e0 = g_off[w], e1 = g_off[w + 1];
    int e = e0;
#pragma unroll 1
    for (; e + 4 <= e1; e += 4) {
        int s0 = __ldg(&g_csr[e]);
        int s1 = __ldg(&g_csr[e + 1]);
        int s2 = __ldg(&g_csr[e + 2]);
        int s3 = __ldg(&g_csr[e + 3]);
        float c0 = isdd * __ldg(&g_isd[s0]);
        float c1 = isdd * __ldg(&g_isd[s1]);
        float c2 = isdd * __ldg(&g_isd[s2]);
        float c3 = isdd * __ldg(&g_isd[s3]);
        const float4* h0 = (const float4*)(h + (size_t)s0 * D);
        const float4* h1 = (const float4*)(h + (size_t)s1 * D);
        const float4* h2 = (const float4*)(h + (size_t)s2 * D);
        const float4* h3 = (const float4*)(h + (size_t)s3 * D);
#pragma unroll
        for (int t = 0; t < NF; t++) {
            float4 v0 = __ldg(&h0[lane + 32 * t]);
            float4 v1 = __ldg(&h1[lane + 32 * t]);
            float4 v2 = __ldg(&h2[lane + 32 * t]);
            float4 v3 = __ldg(&h3[lane + 32 * t]);
            acc[t].x += c0 * v0.x + c1 * v1.x + c2 * v2.x + c3 * v3.x;
            acc[t].y += c0 * v0.y + c1 * v1.y + c2 * v2.y + c3 * v3.y;
            acc[t].z += c0 * v0.z + c1 * v1.z + c2 * v2.z + c3 * v3.z;
            acc[t].w += c0 * v0.w + c1 * v1.w + c2 * v2.w + c3 * v3.w;
        }
    }
#pragma unroll 1
    for (; e < e1; e++) {
        int s0 = __ldg(&g_csr[e]);
        float c0 = isdd * __ldg(&g_isd[s0]);
        const float4* h0 = (const float4*)(h + (size_t)s0 * D);
#pragma unroll
        for (int t = 0; t < NF; t++) {
            float4 v0 = __ldg(&h0[lane + 32 * t]);
            acc[t].x += c0 * v0.x; acc[t].y += c0 * v0.y;
            acc[t].z += c0 * v0.z; acc[t].w += c0 * v0.w;
        }
    }
#pragma unroll
    for (int t = 0; t < NF; t++) {
        int i4 = w * (D / 4) + lane + 32 * t;
        bf16 h0, l0, h1, l1, h2, l2, h3, l3;
        bsplit(acc[t].x, h0, l0); bsplit(acc[t].y, h1, l1);
        bsplit(acc[t].z, h2, l2); bsplit(acc[t].w, h3, l3);
        ((bf162*)oh)[i4 * 2 + 0] = bf162{h0, h1};
        ((bf162*)oh)[i4 * 2 + 1] = bf162{h2, h3};
        ((bf162*)ol)[i4 * 2 + 0] = bf162{l0, l1};
        ((bf162*)ol)[i4 * 2 + 1] = bf162{l2, l3};
    }
}

// ---------------- bf16x2 tensor-core GEMM (cp.async + ldmatrix) -------------
// C[M x 256] = (Ah+Al)[M x K] @ (Bh+Bl)^T   (B planes are [N][K])
// block 128(M) x 128(N), BK=16, 256 threads = 8 warps, warp tile 64x32.
#define SK 24
#define STAGE_BF 12288
#define NSTAGE 4
#define TGB_SMEM (size_t)(NSTAGE * STAGE_BF * sizeof(bf16))  // 98304 B

template <int K, bool GELU, bool STATS, bool PLANES, bool HEAD>
__global__ void __launch_bounds__(256, 2) k_bgemm(
        const bf16* __restrict__ Ah, const bf16* __restrict__ Al,
        const bf16* __restrict__ BhT, const bf16* __restrict__ BlT,
        const float* __restrict__ bias, float* __restrict__ C,
        bf16* __restrict__ Ch, bf16* __restrict__ Cl,
        const float* __restrict__ headw, float* __restrict__ outv, int M) {
    const int BK = 16, NC = K / BK;
    extern __shared__ bf16 smp[];

    int bm = blockIdx.x * 128;
    int bn = blockIdx.y * 128;
    int tid = threadIdx.x;
    int wid = tid >> 5, lane = tid & 31;
    int g = lane >> 2, t = lane & 3;
    int warp_m = (wid & 1) * 64;
    int warp_n = (wid >> 1) * 32;

    int crow = tid >> 1, chalf = (tid & 1) * 8;
    bool arowok = (bm + crow) < M;
    const bf16* gA_h = Ah + (size_t)(arowok ? bm + crow : 0) * K + chalf;
    const bf16* gA_l = Al + (size_t)(arowok ? bm + crow : 0) * K + chalf;
    const bf16* gB_h = BhT + (size_t)(bn + crow) * K + chalf;
    const bf16* gB_l = BlT + (size_t)(bn + crow) * K + chalf;
    int asz = arowok ? 16 : 0;
    uint32_t smbase = smem_u32(smp);
    uint32_t doff = smbase + (uint32_t)(crow * SK + chalf) * 2;

    int l8 = lane & 7, lh = (lane >> 3) & 1, lq = lane >> 4;
    uint32_t a_lane_off = (uint32_t)((warp_m + l8 + lh * 8) * SK + lq * 8) * 2;
    uint32_t b_lane_off = (uint32_t)((warp_n + l8) * SK + lh * 8) * 2;

    float acc[4][4][4];
#pragma unroll
    for (int m = 0; m < 4; m++)
#pragma unroll
        for (int n = 0; n < 4; n++)
#pragma unroll
            for (int c = 0; c < 4; c++) acc[m][n][c] = 0.f;

#define ISSUE(s)                                                       \
    do {                                                               \
        uint32_t b_ = doff + (uint32_t)(((s) & 3) * STAGE_BF) * 2;     \
        int k0_ = (s) * BK;                                            \
        cpa16(b_, gA_h + k0_, asz);                                    \
        cpa16(b_ + 3072 * 2, gA_l + k0_, asz);                         \
        cpa16(b_ + 6144 * 2, gB_h + k0_, 16);                          \
        cpa16(b_ + 9216 * 2, gB_l + k0_, 16);                          \
        asm volatile("cp.async.commit_group;" ::: "memory");           \
    } while (0)

    ISSUE(0); ISSUE(1); ISSUE(2);

#pragma unroll 1
    for (int c = 0; c < NC; c++) {
        if (c + 2 < NC) {
            asm volatile("cp.async.wait_group 2;" ::: "memory");
        } else if (c + 1 < NC) {
            asm volatile("cp.async.wait_group 1;" ::: "memory");
        } else {
            asm volatile("cp.async.wait_group 0;" ::: "memory");
        }
        __syncthreads();
        if (c + 3 < NC) ISSUE(c + 3);

        uint32_t st = smbase + (uint32_t)((c & 3) * STAGE_BF) * 2;
        uint32_t aaH = st + a_lane_off;
        uint32_t baH = st + 6144 * 2 + b_lane_off;

        unsigned bH[4][2], bL[4][2];
#pragma unroll
        for (int n = 0; n < 4; n++) {
            uint32_t ad = baH + (uint32_t)(n * 8 * SK) * 2;
            LDSM2(bH[n][0], bH[n][1], ad);
            LDSM2(bL[n][0], bL[n][1], ad + 3072 * 2);
        }
#pragma unroll
        for (int m = 0; m < 4; m++) {
            uint32_t ad = aaH + (uint32_t)(m * 16 * SK) * 2;
            unsigned aH0, aH1, aH2, aH3, aL0, aL1, aL2, aL3;
            LDSM4(aH0, aH1, aH2, aH3, ad);
            LDSM4(aL0, aL1, aL2, aL3, ad + 3072 * 2);
#pragma unroll
            for (int n = 0; n < 4; n++) {
                float* cc = acc[m][n];
                mma_bf16(cc[0], cc[1], cc[2], cc[3],
                         aH0, aH1, aH2, aH3, bL[n][0], bL[n][1]);
                mma_bf16(cc[0], cc[1], cc[2], cc[3],
                         aL0, aL1, aL2, aL3, bH[n][0], bH[n][1]);
                mma_bf16(cc[0], cc[1], cc[2], cc[3],
                         aH0, aH1, aH2, aH3, bH[n][0], bH[n][1]);
            }
        }
    }
#undef ISSUE

    // ---- epilogue ----
    float s_sum[4][2], s_sq[4][2];
    if (STATS) {
#pragma unroll
        for (int n = 0; n < 4; n++)
#pragma unroll
            for (int p = 0; p < 2; p++) { s_sum[n][p] = 0.f; s_sq[n][p] = 0.f; }
    }
    float rsum[4][2];
    if (HEAD) {
#pragma unroll
        for (int m = 0; m < 4; m++) { rsum[m][0] = 0.f; rsum[m][1] = 0.f; }
    }
#pragma unroll
    for (int m = 0; m < 4; m++) {
        int row0 = bm + warp_m + m * 16;
#pragma unroll
        for (int n = 0; n < 4; n++) {
            int col = bn + warp_n + n * 8 + t * 2;
            float b0 = __ldg(&bias[col]), b1 = __ldg(&bias[col + 1]);
            float w0, w1;
            if (HEAD) { w0 = __ldg(&headw[col]); w1 = __ldg(&headw[col + 1]); }
#pragma unroll
            for (int half = 0; half < 2; half++) {
                int r = row0 + g + half * 8;
                if (r >= M) continue;
                float2 o = make_float2(acc[m][n][half * 2 + 0] + b0,
                                       acc[m][n][half * 2 + 1] + b1);
                if (STATS) {
                    s_sum[n][0] += o.x; s_sq[n][0] += o.x * o.x;
                    s_sum[n][1] += o.y; s_sq[n][1] += o.y * o.y;
                }
                if (GELU) { o.x = gelu_tanh(o.x); o.y = gelu_tanh(o.y); }
                if (HEAD) {
                    rsum[m][half] += o.x * w0 + o.y * w1;
                } else if (PLANES) {
                    bf16 h0, l0, h1, l1;
                    bsplit(o.x, h0, l0); bsplit(o.y, h1, l1);
                    *(bf162*)(Ch + (size_t)r * DH + col) = bf162{h0, h1};
                    *(bf162*)(Cl + (size_t)r * DH + col) = bf162{l0, l1};
                } else {
                    *(float2*)(C + (size_t)r * DH + col) = o;
                }
            }
        }
    }
    if (HEAD) {
#pragma unroll
        for (int m = 0; m < 4; m++)
#pragma unroll
            for (int half = 0; half < 2; half++) {
                float v = rsum[m][half];
                v += __shfl_xor_sync(0xffffffffu, v, 1);
                v += __shfl_xor_sync(0xffffffffu, v, 2);
                int r = bm + warp_m + m * 16 + g + half * 8;
                if (t == 0 && r < M) atomicAdd(&outv[r], v);
            }
    }
    if (STATS) {
#pragma unroll
        for (int n = 0; n < 4; n++)
#pragma unroll
            for (int p = 0; p < 2; p++) {
#pragma unroll
                for (int off = 4; off < 32; off <<= 1) {
                    s_sum[n][p] += __shfl_xor_sync(0xffffffffu, s_sum[n][p], off);
                    s_sq[n][p] += __shfl_xor_sync(0xffffffffu, s_sq[n][p], off);
                }
            }
        if (lane < 4) {
#pragma unroll
            for (int n = 0; n < 4; n++)
#pragma unroll
                for (int p = 0; p < 2; p++) {
                    int col = bn + warp_n + n * 8 + lane * 2 + p;
                    atomicAdd(&g_stats[col], (double)s_sum[n][p]);
                    atomicAdd(&g_stats[DH + col], (double)s_sq[n][p]);
                }
        }
    }
}

// ---------------- batchnorm -------------------------------------------------
__global__ void k_zero_stats() {
    int i = blockIdx.x * blockDim.x + threadIdx.x;
    if (i < 2 * DH) g_stats[i] = 0.0;
}

// bn_final fused: per-thread scale/shift from g_stats.
// MODE 0: fp32 out; MODE 1: bf16 planes out only
template <int MODE>
__global__ void k_bn_apply(const float* __restrict__ m, const float* __restrict__ res,
                           float* __restrict__ hout, bf16* __restrict__ oh,
                           bf16* __restrict__ ol,
                           const float* __restrict__ gamma,
                           const float* __restrict__ beta) {
    int idx = blockIdx.x * blockDim.x + threadIdx.x;  // float4 index
    if (idx >= NN * (DH / 4)) return;
    int c4 = (idx & (DH / 4 - 1)) * 4;
    float sc[4], sh[4];
#pragma unroll
    for (int j = 0; j < 4; j++) {
        double mean = g_stats[c4 + j] * (1.0 / NN);
        double var = g_stats[DH + c4 + j] * (1.0 / NN) - mean * mean;
        float s = __ldg(&gamma[c4 + j]) * rsqrtf((float)var + 1e-5f);
        sc[j] = s;
        sh[j] = __ldg(&beta[c4 + j]) - (float)mean * s;
    }
    float4 v = ((const float4*)m)[idx];
    float4 r = ((const float4*)res)[idx];
    float4 o;
    o.x = gelu_tanh(v.x * sc[0] + sh[0]) + r.x;
    o.y = gelu_tanh(v.y * sc[1] + sh[1]) + r.y;
    o.z = gelu_tanh(v.z * sc[2] + sh[2]) + r.z;
    o.w = gelu_tanh(v.w * sc[3] + sh[3]) + r.w;
    if (MODE == 0) {
        ((float4*)hout)[idx] = o;
    } else {
        bf16 h0, l0, h1, l1, h2, l2, h3, l3;
        bsplit(o.x, h0, l0); bsplit(o.y, h1, l1);
        bsplit(o.z, h2, l2); bsplit(o.w, h3, l3);
        ((bf162*)oh)[idx * 2 + 0] = bf162{h0, h1};
        ((bf162*)oh)[idx * 2 + 1] = bf162{h2, h3};
        ((bf162*)ol)[idx * 2 + 0] = bf162{l0, l1};
        ((bf162*)ol)[idx * 2 + 1] = bf162{l2, l3};
    }
}

// ---------------- launch -----------------------------------------------------
extern "C" void kernel_launch(void* const* d_in, const int* in_sizes, int n_in,
                              void* d_out, int out_size) {
    const float* x = (const float*)d_in[0];
    const int* ei = (const int*)d_in[1];
    const int* mask = (const int*)d_in[2];
    const float* conv_w0 = (const float*)d_in[3];
    const float* conv_b0 = (const float*)d_in[4];
    const float* conv_w1 = (const float*)d_in[5];
    const float* conv_b1 = (const float*)d_in[6];
    const float* conv_w2 = (const float*)d_in[7];
    const float* conv_b2 = (const float*)d_in[8];
    const float* bn_g0 = (const float*)d_in[9];
    const float* bn_b0 = (const float*)d_in[10];
    const float* bn_g1 = (const float*)d_in[11];
    const float* bn_b1 = (const float*)d_in[12];
    const float* bn_g2 = (const float*)d_in[13];
    const float* bn_b2 = (const float*)d_in[14];
    const float* proj_w = (const float*)d_in[15];
    const float* proj_b = (const float*)d_in[16];
    const float* lin_w0 = (const float*)d_in[17];
    const float* lin_b0 = (const float*)d_in[18];
    const float* lin_w1 = (const float*)d_in[19];
    const float* lin_b1 = (const float*)d_in[20];
    const float* head_w = (const float*)d_in[21];
    const float* head_b = (const float*)d_in[22];
    float* out = (float*)d_out;

    const int* src = ei;
    const int* dst = ei + EE;

    float *p_h, *p_m, *p_res;
    bf16 *p1h, *p1l, *p2h, *p2l, *wh, *wl;
    cudaGetSymbolAddress((void**)&p_h, g_h);
    cudaGetSymbolAddress((void**)&p_m, g_m);
    cudaGetSymbolAddress((void**)&p_res, g_res);
    cudaGetSymbolAddress((void**)&p1h, g_p1h);
    cudaGetSymbolAddress((void**)&p1l, g_p1l);
    cudaGetSymbolAddress((void**)&p2h, g_p2h);
    cudaGetSymbolAddress((void**)&p2l, g_p2l);
    cudaGetSymbolAddress((void**)&wh, g_wh);
    cudaGetSymbolAddress((void**)&wl, g_wl);

    cudaFuncSetAttribute(k_bgemm<DIN, false, false, false, false>, cudaFuncAttributeMaxDynamicSharedMemorySize, (int)TGB_SMEM);
    cudaFuncSetAttribute(k_bgemm<DIN, false, true, false, false>, cudaFuncAttributeMaxDynamicSharedMemorySize, (int)TGB_SMEM);
    cudaFuncSetAttribute(k_bgemm<DH, false, true, false, false>, cudaFuncAttributeMaxDynamicSharedMemorySize, (int)TGB_SMEM);
    cudaFuncSetAttribute(k_bgemm<DH, true, false, true, false>, cudaFuncAttributeMaxDynamicSharedMemorySize, (int)TGB_SMEM);
    cudaFuncSetAttribute(k_bgemm<DH, true, false, false, true>, cudaFuncAttributeMaxDynamicSharedMemorySize, (int)TGB_SMEM);

    const int T = 256;
    const int WSTRIDE = DH * DH;
    dim3 tg_grid((NN + 127) / 128, 2);  // 391 x 2
    int ew4_256 = NN * (DH / 4);
    int gather_blocks = (NN * 32 + T - 1) / T;

    // ---- fork a side stream (host objects only) ----
    cudaStream_t s1;
    cudaEvent_t e0, e1;
    cudaStreamCreateWithFlags(&s1, cudaStreamNonBlocking);
    cudaEventCreateWithFlags(&e0, cudaEventDisableTiming);
    cudaEventCreateWithFlags(&e1, cudaEventDisableTiming);

    cudaEventRecord(e0, 0);
    cudaStreamWaitEvent(s1, e0, 0);

    // side stream: CSR build + degrees + layer-0 gather + stats zero + out zero
    k_zero_cnt<<<(NN + T - 1) / T, T, 0, s1>>>();
    k_deg_count<<<(EE + T - 1) / T, T, 0, s1>>>(dst);
    k_deg_final<<<(NN + T - 1) / T, T, 0, s1>>>();
    k_scan1<<<SCAN_B, 1024, 0, s1>>>();
    k_scan2<<<1, 64, 0, s1>>>();
    k_scan3<<<SCAN_B, 1024, 0, s1>>>();
    k_csr_fill<<<(EE + T - 1) / T, T, 0, s1>>>(src, dst);
    k_gather<DIN><<<gather_blocks, T, 0, s1>>>(x, p2h, p2l);
    k_zero_stats<<<2, T, 0, s1>>>();
    k_zero_out<<<(NN + T - 1) / T, T, 0, s1>>>(out);
    cudaEventRecord(e1, s1);

    // main stream: splits + proj GEMM (independent of CSR)
    k_split_x<<<(NN * DIN / 4 + T - 1) / T, T>>>(x, p1h, p1l);
    k_split_w<<<(DIN * DH + T - 1) / T, T>>>(proj_w, DIN, wh + 0 * WSTRIDE, wl + 0 * WSTRIDE);
    k_split_w<<<(DIN * DH + T - 1) / T, T>>>(conv_w0, DIN, wh + 1 * WSTRIDE, wl + 1 * WSTRIDE);
    k_split_w<<<(DH * DH + T - 1) / T, T>>>(conv_w1, DH, wh + 2 * WSTRIDE, wl + 2 * WSTRIDE);
    k_split_w<<<(DH * DH + T - 1) / T, T>>>(conv_w2, DH, wh + 3 * WSTRIDE, wl + 3 * WSTRIDE);
    k_split_w<<<(DH * DH + T - 1) / T, T>>>(lin_w0, DH, wh + 4 * WSTRIDE, wl + 4 * WSTRIDE);
    k_split_w<<<(DH * DH + T - 1) / T, T>>>(lin_w1, DH, wh + 5 * WSTRIDE, wl + 5 * WSTRIDE);
    k_bgemm<DIN, false, false, false, false><<<tg_grid, T, TGB_SMEM>>>(
        p1h, p1l, wh + 0 * WSTRIDE, wl + 0 * WSTRIDE, proj_b, p_res, nullptr, nullptr,
        nullptr, nullptr, NN);

    // join
    cudaStreamWaitEvent(0, e1, 0);

    // ---- GCN layer 0 ----
    k_bgemm<DIN, false, true, false, false><<<tg_grid, T, TGB_SMEM>>>(
        p2h, p2l, wh + 1 * WSTRIDE, wl + 1 * WSTRIDE, conv_b0, p_m, nullptr, nullptr,
        nullptr, nullptr, NN);
    k_bn_apply<0><<<(ew4_256 + T - 1) / T, T>>>(p_m, p_res, p_h, nullptr, nullptr, bn_g0, bn_b0);
    k_zero_stats<<<2, T>>>();

    // ---- GCN layer 1 ----
    k_gather<DH><<<gather_blocks, T>>>(p_h, p2h, p2l);
    k_bgemm<DH, false, true, false, false><<<tg_grid, T, TGB_SMEM>>>(
        p2h, p2l, wh + 2 * WSTRIDE, wl + 2 * WSTRIDE, conv_b1, p_m, nullptr, nullptr,
        nullptr, nullptr, NN);
    k_bn_apply<0><<<(ew4_256 + T - 1) / T, T>>>(p_m, p_h, p_h, nullptr, nullptr, bn_g1, bn_b1);
    k_zero_stats<<<2, T>>>();

    // ---- GCN layer 2 ----
    k_gather<DH><<<gather_blocks, T>>>(p_h, p2h, p2l);
    k_bgemm<DH, false, true, false, false><<<tg_grid, T, TGB_SMEM>>>(
        p2h, p2l, wh + 3 * WSTRIDE, wl + 3 * WSTRIDE, conv_b2, p_m, nullptr, nullptr,
        nullptr, nullptr, NN);
    k_bn_apply<1><<<(ew4_256 + T - 1) / T, T>>>(p_m, p_h, nullptr, p1h, p1l, bn_g2, bn_b2);

    // ---- MLP + fused head ----
    k_bgemm<DH, true, false, true, false><<<tg_grid, T, TGB_SMEM>>>(
        p1h, p1l, wh + 4 * WSTRIDE, wl + 4 * WSTRIDE, lin_b0, nullptr, p2h, p2l,
        nullptr, nullptr, NN);
    k_bgemm<DH, true, false, false, true><<<tg_grid, T, TGB_SMEM>>>(
        p2h, p2l, wh + 5 * WSTRIDE, wl + 5 * WSTRIDE, lin_b1, nullptr, nullptr, nullptr,
        head_w, out, NN);

    // ---- mask + bias ----
    k_mask_out<<<(NN + T - 1) / T, T>>>(out, mask, head_b);
}

// round 15
// speedup vs baseline: 1.4052x; 1.4052x over previous
#include <cuda_runtime.h>
#include <cuda_bf16.h>
#include <math.h>
#include <stdint.h>

#define NN 50000
#define EE 800000
#define DIN 128
#define DH 256
#define SCAN_B 49  // ceil(NN/1024)

typedef __nv_bfloat16 bf16;
typedef __nv_bfloat162 bf162;

// ---------------- scratch (static device globals; no allocations) -----------
__device__ __align__(16) float g_h[NN * DH];
__device__ __align__(16) float g_m[NN * DH];
__device__ __align__(16) float g_res[NN * DH];
__device__ __align__(16) bf16  g_p1h[NN * DH];
__device__ __align__(16) bf16  g_p1l[NN * DH];
__device__ __align__(16) bf16  g_p2h[NN * DH];
__device__ __align__(16) bf16  g_p2l[NN * DH];
__device__ __align__(16) bf16  g_wh[6 * DH * DH];  // transposed [N][K] hi planes
__device__ __align__(16) bf16  g_wl[6 * DH * DH];
__device__ __align__(16) int   g_cnt[NN];
__device__ __align__(16) int   g_off[NN + 1];
__device__ __align__(16) int   g_cursor[NN];
__device__ __align__(16) int   g_csr[EE];
__device__ __align__(16) int   g_bsum[64];
__device__ __align__(16) int   g_bbase[64];
__device__ __align__(16) float g_isd[NN];
__device__ __align__(16) float g_id[NN];
__device__ __align__(16) double g_stats[2 * DH];
__device__ __align__(16) float g_scale[DH];
__device__ __align__(16) float g_shift[DH];

// ---------------- helpers ---------------------------------------------------
__device__ __forceinline__ float gelu_tanh(float x) {
    float x3 = x * x * x;
    return 0.5f * x * (1.0f + tanhf(0.7978845608028654f * (x + 0.044715f * x3)));
}

__device__ __forceinline__ void bsplit(float x, bf16& h, bf16& l) {
    h = __float2bfloat16_rn(x);
    l = __float2bfloat16_rn(x - __bfloat162float(h));
}

__device__ __forceinline__ uint32_t smem_u32(const void* p) {
    uint32_t a;
    asm("{ .reg .u64 t; cvta.to.shared.u64 t, %1; cvt.u32.u64 %0, t; }" : "=r"(a) : "l"(p));
    return a;
}

__device__ __forceinline__ void mma_bf16(float& c0, float& c1, float& c2, float& c3,
                                         unsigned a0, unsigned a1, unsigned a2, unsigned a3,
                                         unsigned b0, unsigned b1) {
    asm volatile("mma.sync.aligned.m16n8k16.row.col.f32.bf16.bf16.f32 "
                 "{%0,%1,%2,%3},{%4,%5,%6,%7},{%8,%9},{%0,%1,%2,%3};"
                 : "+f"(c0), "+f"(c1), "+f"(c2), "+f"(c3)
                 : "r"(a0), "r"(a1), "r"(a2), "r"(a3), "r"(b0), "r"(b1));
}

__device__ __forceinline__ void cpa16(uint32_t d, const void* s, int srcsz) {
    asm volatile("cp.async.ca.shared.global [%0], [%1], 16, %2;"
                 :: "r"(d), "l"(s), "r"(srcsz) : "memory");
}

#define LDSM4(r0, r1, r2, r3, addr)                                            \
    asm volatile("ldmatrix.sync.aligned.m8n8.x4.shared.b16 {%0,%1,%2,%3}, [%4];" \
                 : "=r"(r0), "=r"(r1), "=r"(r2), "=r"(r3) : "r"(addr))
#define LDSM2(r0, r1, addr)                                                    \
    asm volatile("ldmatrix.sync.aligned.m8n8.x2.shared.b16 {%0,%1}, [%2];"     \
                 : "=r"(r0), "=r"(r1) : "r"(addr))

// ---------------- degree + CSR ----------------------------------------------
__global__ void k_zero_cnt() {
    int i = blockIdx.x * blockDim.x + threadIdx.x;
    if (i < NN) g_cnt[i] = 0;
}

__global__ void k_deg_count(const int* __restrict__ dst) {
    int e = blockIdx.x * blockDim.x + threadIdx.x;
    if (e < EE) atomicAdd(&g_cnt[dst[e]], 1);
}

__global__ void k_deg_final() {
    int i = blockIdx.x * blockDim.x + threadIdx.x;
    if (i < NN) {
        float d = (float)g_cnt[i] + 1.0f;
        g_isd[i] = rsqrtf(d);
        g_id[i] = 1.0f / d;
    }
}

__global__ void k_scan1() {
    __shared__ int sm[1024];
    int tid = threadIdx.x;
    int i = blockIdx.x * 1024 + tid;
    int v = (i < NN) ? g_cnt[i] : 0;
    sm[tid] = v;
    __syncthreads();
#pragma unroll
    for (int off = 1; off < 1024; off <<= 1) {
        int t = (tid >= off) ? sm[tid - off] : 0;
        __syncthreads();
        sm[tid] += t;
        __syncthreads();
    }
    if (i < NN) g_off[i + 1] = sm[tid];
    if (tid == 1023) g_bsum[blockIdx.x] = sm[1023];
}

__global__ void k_scan2() {
    __shared__ int sm[64];
    int tid = threadIdx.x;
    int v = (tid < SCAN_B) ? g_bsum[tid] : 0;
    sm[tid] = v;
    __syncthreads();
#pragma unroll
    for (int off = 1; off < 64; off <<= 1) {
        int t = (tid >= off) ? sm[tid - off] : 0;
        __syncthreads();
        sm[tid] += t;
        __syncthreads();
    }
    if (tid < SCAN_B) g_bbase[tid] = sm[tid] - v;
}

__global__ void k_scan3() {
    int i = blockIdx.x * 1024 + threadIdx.x;
    if (i < NN) {
        int incl = g_off[i + 1] + g_bbase[blockIdx.x];
        g_off[i + 1] = incl;
        g_cursor[i] = incl - g_cnt[i];
    }
    if (i == 0) g_off[0] = 0;
}

__global__ void k_csr_fill(const int* __restrict__ src, const int* __restrict__ dst) {
    int e = blockIdx.x * blockDim.x + threadIdx.x;
    if (e < EE) {
        int p = atomicAdd(&g_cursor[dst[e]], 1);
        g_csr[p] = src[e];
    }
}

// ---------------- splitting producers ---------------------------------------
__global__ void k_split_x(const float* __restrict__ x, bf16* __restrict__ oh,
                          bf16* __restrict__ ol) {
    int idx = blockIdx.x * blockDim.x + threadIdx.x;  // float4 index
    if (idx >= NN * (DIN / 4)) return;
    float4 v = ((const float4*)x)[idx];
    bf16 h0, l0, h1, l1, h2, l2, h3, l3;
    bsplit(v.x, h0, l0); bsplit(v.y, h1, l1);
    bsplit(v.z, h2, l2); bsplit(v.w, h3, l3);
    ((bf162*)oh)[idx * 2 + 0] = bf162{h0, h1};
    ((bf162*)oh)[idx * 2 + 1] = bf162{h2, h3};
    ((bf162*)ol)[idx * 2 + 0] = bf162{l0, l1};
    ((bf162*)ol)[idx * 2 + 1] = bf162{l2, l3};
}

__global__ void k_split_w(const float* __restrict__ W, int K,
                          bf16* __restrict__ oh, bf16* __restrict__ ol) {
    int idx = blockIdx.x * blockDim.x + threadIdx.x;
    if (idx >= K * DH) return;
    int k = idx / DH, n = idx % DH;
    bf16 h, l;
    bsplit(W[idx], h, l);
    oh[n * K + k] = h;
    ol[n * K + k] = l;
}

__global__ void k_zero_out(float* __restrict__ out) {
    int i = blockIdx.x * blockDim.x + threadIdx.x;
    if (i < NN) out[i] = 0.0f;
}

__global__ void k_mask_out(float* __restrict__ out, const int* __restrict__ mask,
                           const float* __restrict__ hb) {
    int i = blockIdx.x * blockDim.x + threadIdx.x;
    if (i < NN) out[i] = (mask[i] != 0) ? (out[i] + __ldg(&hb[0])) : 0.0f;
}

// ---------------- aggregation: warp-per-node CSR gather -> planes -----------
template <int D>
__global__ void k_gather(const float* __restrict__ h, bf16* __restrict__ oh,
                         bf16* __restrict__ ol) {
    int w = (blockIdx.x * blockDim.x + threadIdx.x) >> 5;
    int lane = threadIdx.x & 31;
    if (w >= NN) return;
    const int NF = D / 128;
    const float4* hn = (const float4*)(h + (size_t)w * D);
    float idg = g_id[w], isdd = g_isd[w];
    float4 acc[NF];
#pragma unroll
    for (int t = 0; t < NF; t++) {
        float4 v = hn[lane + 32 * t];
        acc[t] = make_float4(v.x * idg, v.y * idg, v.z * idg, v.w * idg);
    }
    int e0 = g_off[w], e1 = g_off[w + 1];
    int e = e0;
#pragma unroll 1
    for (; e + 2 <= e1; e += 2) {
        int s0 = __ldg(&g_csr[e]);
        int s1 = __ldg(&g_csr[e + 1]);
        float c0 = isdd * __ldg(&g_isd[s0]);
        float c1 = isdd * __ldg(&g_isd[s1]);
        const float4* h0 = (const float4*)(h + (size_t)s0 * D);
        const float4* h1 = (const float4*)(h + (size_t)s1 * D);
#pragma unroll
        for (int t = 0; t < NF; t++) {
            float4 v0 = __ldg(&h0[lane + 32 * t]);
            float4 v1 = __ldg(&h1[lane + 32 * t]);
            acc[t].x += c0 * v0.x + c1 * v1.x;
            acc[t].y += c0 * v0.y + c1 * v1.y;
            acc[t].z += c0 * v0.z + c1 * v1.z;
            acc[t].w += c0 * v0.w + c1 * v1.w;
        }
    }
    if (e < e1) {
        int s0 = __ldg(&g_csr[e]);
        float c0 = isdd * __ldg(&g_isd[s0]);
        const float4* h0 = (const float4*)(h + (size_t)s0 * D);
#pragma unroll
        for (int t = 0; t < NF; t++) {
            float4 v0 = __ldg(&h0[lane + 32 * t]);
            acc[t].x += c0 * v0.x; acc[t].y += c0 * v0.y;
            acc[t].z += c0 * v0.z; acc[t].w += c0 * v0.w;
        }
    }
#pragma unroll
    for (int t = 0; t < NF; t++) {
        int i4 = w * (D / 4) + lane + 32 * t;
        bf16 h0, l0, h1, l1, h2, l2, h3, l3;
        bsplit(acc[t].x, h0, l0); bsplit(acc[t].y, h1, l1);
        bsplit(acc[t].z, h2, l2); bsplit(acc[t].w, h3, l3);
        ((bf162*)oh)[i4 * 2 + 0] = bf162{h0, h1};
        ((bf162*)oh)[i4 * 2 + 1] = bf162{h2, h3};
        ((bf162*)ol)[i4 * 2 + 0] = bf162{l0, l1};
        ((bf162*)ol)[i4 * 2 + 1] = bf162{l2, l3};
    }
}

// ---------------- bf16x2 tensor-core GEMM (cp.async + ldmatrix) -------------
// C[M x 256] = (Ah+Al)[M x K] @ (Bh+Bl)^T   (B planes are [N][K])
// block 128(M) x 128(N), BK=16, 256 threads = 8 warps, warp tile 64x32.
#define SK 24
#define STAGE_BF 12288
#define NSTAGE 4
#define TGB_SMEM (size_t)(NSTAGE * STAGE_BF * sizeof(bf16))  // 98304 B

template <int K, bool GELU, bool STATS, bool PLANES, bool HEAD>
__global__ void __launch_bounds__(256, 2) k_bgemm(
        const bf16* __restrict__ Ah, const bf16* __restrict__ Al,
        const bf16* __restrict__ BhT, const bf16* __restrict__ BlT,
        const float* __restrict__ bias, float* __restrict__ C,
        bf16* __restrict__ Ch, bf16* __restrict__ Cl,
        const float* __restrict__ headw, float* __restrict__ outv, int M) {
    const int BK = 16, NC = K / BK;
    extern __shared__ bf16 smp[];

    int bm = blockIdx.x * 128;
    int bn = blockIdx.y * 128;
    int tid = threadIdx.x;
    int wid = tid >> 5, lane = tid & 31;
    int g = lane >> 2, t = lane & 3;
    int warp_m = (wid & 1) * 64;
    int warp_n = (wid >> 1) * 32;

    int crow = tid >> 1, chalf = (tid & 1) * 8;
    bool arowok = (bm + crow) < M;
    const bf16* gA_h = Ah + (size_t)(arowok ? bm + crow : 0) * K + chalf;
    const bf16* gA_l = Al + (size_t)(arowok ? bm + crow : 0) * K + chalf;
    const bf16* gB_h = BhT + (size_t)(bn + crow) * K + chalf;
    const bf16* gB_l = BlT + (size_t)(bn + crow) * K + chalf;
    int asz = arowok ? 16 : 0;
    uint32_t smbase = smem_u32(smp);
    uint32_t doff = smbase + (uint32_t)(crow * SK + chalf) * 2;

    int l8 = lane & 7, lh = (lane >> 3) & 1, lq = lane >> 4;
    uint32_t a_lane_off = (uint32_t)((warp_m + l8 + lh * 8) * SK + lq * 8) * 2;
    uint32_t b_lane_off = (uint32_t)((warp_n + l8) * SK + lh * 8) * 2;

    float acc[4][4][4];
#pragma unroll
    for (int m = 0; m < 4; m++)
#pragma unroll
        for (int n = 0; n < 4; n++)
#pragma unroll
            for (int c = 0; c < 4; c++) acc[m][n][c] = 0.f;

#define ISSUE(s)                                                       \
    do {                                                               \
        uint32_t b_ = doff + (uint32_t)(((s) & 3) * STAGE_BF) * 2;     \
        int k0_ = (s) * BK;                                            \
        cpa16(b_, gA_h + k0_, asz);                                    \
        cpa16(b_ + 3072 * 2, gA_l + k0_, asz);                         \
        cpa16(b_ + 6144 * 2, gB_h + k0_, 16);                          \
        cpa16(b_ + 9216 * 2, gB_l + k0_, 16);                          \
        asm volatile("cp.async.commit_group;" ::: "memory");           \
    } while (0)

    ISSUE(0); ISSUE(1); ISSUE(2);

#pragma unroll 1
    for (int c = 0; c < NC; c++) {
        if (c + 2 < NC) {
            asm volatile("cp.async.wait_group 2;" ::: "memory");
        } else if (c + 1 < NC) {
            asm volatile("cp.async.wait_group 1;" ::: "memory");
        } else {
            asm volatile("cp.async.wait_group 0;" ::: "memory");
        }
        __syncthreads();
        if (c + 3 < NC) ISSUE(c + 3);

        uint32_t st = smbase + (uint32_t)((c & 3) * STAGE_BF) * 2;
        uint32_t aaH = st + a_lane_off;
        uint32_t baH = st + 6144 * 2 + b_lane_off;

        unsigned bH[4][2], bL[4][2];
#pragma unroll
        for (int n = 0; n < 4; n++) {
            uint32_t ad = baH + (uint32_t)(n * 8 * SK) * 2;
            LDSM2(bH[n][0], bH[n][1], ad);
            LDSM2(bL[n][0], bL[n][1], ad + 3072 * 2);
        }
#pragma unroll
        for (int m = 0; m < 4; m++) {
            uint32_t ad = aaH + (uint32_t)(m * 16 * SK) * 2;
            unsigned aH0, aH1, aH2, aH3, aL0, aL1, aL2, aL3;
            LDSM4(aH0, aH1, aH2, aH3, ad);
            LDSM4(aL0, aL1, aL2, aL3, ad + 3072 * 2);
#pragma unroll
            for (int n = 0; n < 4; n++) {
                float* cc = acc[m][n];
                mma_bf16(cc[0], cc[1], cc[2], cc[3],
                         aH0, aH1, aH2, aH3, bL[n][0], bL[n][1]);
                mma_bf16(cc[0], cc[1], cc[2], cc[3],
                         aL0, aL1, aL2, aL3, bH[n][0], bH[n][1]);
                mma_bf16(cc[0], cc[1], cc[2], cc[3],
                         aH0, aH1, aH2, aH3, bH[n][0], bH[n][1]);
            }
        }
    }
#undef ISSUE

    // ---- epilogue ----
    float s_sum[4][2], s_sq[4][2];
    if (STATS) {
#pragma unroll
        for (int n = 0; n < 4; n++)
#pragma unroll
            for (int p = 0; p < 2; p++) { s_sum[n][p] = 0.f; s_sq[n][p] = 0.f; }
    }
    float rsum[4][2];
    if (HEAD) {
#pragma unroll
        for (int m = 0; m < 4; m++) { rsum[m][0] = 0.f; rsum[m][1] = 0.f; }
    }
#pragma unroll
    for (int m = 0; m < 4; m++) {
        int row0 = bm + warp_m + m * 16;
#pragma unroll
        for (int n = 0; n < 4; n++) {
            int col = bn + warp_n + n * 8 + t * 2;
            float b0 = __ldg(&bias[col]), b1 = __ldg(&bias[col + 1]);
            float w0, w1;
            if (HEAD) { w0 = __ldg(&headw[col]); w1 = __ldg(&headw[col + 1]); }
#pragma unroll
            for (int half = 0; half < 2; half++) {
                int r = row0 + g + half * 8;
                if (r >= M) continue;
                float2 o = make_float2(acc[m][n][half * 2 + 0] + b0,
                                       acc[m][n][half * 2 + 1] + b1);
                if (STATS) {
                    s_sum[n][0] += o.x; s_sq[n][0] += o.x * o.x;
                    s_sum[n][1] += o.y; s_sq[n][1] += o.y * o.y;
                }
                if (GELU) { o.x = gelu_tanh(o.x); o.y = gelu_tanh(o.y); }
                if (HEAD) {
                    rsum[m][half] += o.x * w0 + o.y * w1;
                } else if (PLANES) {
                    bf16 h0, l0, h1, l1;
                    bsplit(o.x, h0, l0); bsplit(o.y, h1, l1);
                    *(bf162*)(Ch + (size_t)r * DH + col) = bf162{h0, h1};
                    *(bf162*)(Cl + (size_t)r * DH + col) = bf162{l0, l1};
                } else {
                    *(float2*)(C + (size_t)r * DH + col) = o;
                }
            }
        }
    }
    if (HEAD) {
#pragma unroll
        for (int m = 0; m < 4; m++)
#pragma unroll
            for (int half = 0; half < 2; half++) {
                float v = rsum[m][half];
                v += __shfl_xor_sync(0xffffffffu, v, 1);
                v += __shfl_xor_sync(0xffffffffu, v, 2);
                int r = bm + warp_m + m * 16 + g + half * 8;
                if (t == 0 && r < M) atomicAdd(&outv[r], v);
            }
    }
    if (STATS) {
#pragma unroll
        for (int n = 0; n < 4; n++)
#pragma unroll
            for (int p = 0; p < 2; p++) {
#pragma unroll
                for (int off = 4; off < 32; off <<= 1) {
                    s_sum[n][p] += __shfl_xor_sync(0xffffffffu, s_sum[n][p], off);
                    s_sq[n][p] += __shfl_xor_sync(0xffffffffu, s_sq[n][p], off);
                }
            }
        if (lane < 4) {
#pragma unroll
            for (int n = 0; n < 4; n++)
#pragma unroll
                for (int p = 0; p < 2; p++) {
                    int col = bn + warp_n + n * 8 + lane * 2 + p;
                    atomicAdd(&g_stats[col], (double)s_sum[n][p]);
                    atomicAdd(&g_stats[DH + col], (double)s_sq[n][p]);
                }
        }
    }
}

// ---------------- batchnorm -------------------------------------------------
__global__ void k_zero_stats() {
    int i = blockIdx.x * blockDim.x + threadIdx.x;
    if (i < 2 * DH) g_stats[i] = 0.0;
}

__global__ void k_bn_final(const float* __restrict__ gamma, const float* __restrict__ beta) {
    int c = threadIdx.x;
    double mean = g_stats[c] / (double)NN;
    double var = g_stats[DH + c] / (double)NN - mean * mean;
    double sc = (double)gamma[c] / sqrt(var + 1e-5);
    g_scale[c] = (float)sc;
    g_shift[c] = (float)((double)beta[c] - mean * sc);
}

// MODE 0: fp32 out; MODE 1: bf16 planes out only
template <int MODE>
__global__ void k_bn_apply(const float* __restrict__ m, const float* __restrict__ res,
                           float* __restrict__ hout, bf16* __restrict__ oh,
                           bf16* __restrict__ ol) {
    int idx = blockIdx.x * blockDim.x + threadIdx.x;  // float4 index
    if (idx >= NN * (DH / 4)) return;
    int c4 = (idx & (DH / 4 - 1)) * 4;
    float4 v = ((const float4*)m)[idx];
    float4 r = ((const float4*)res)[idx];
    float4 o;
    o.x = gelu_tanh(v.x * g_scale[c4 + 0] + g_shift[c4 + 0]) + r.x;
    o.y = gelu_tanh(v.y * g_scale[c4 + 1] + g_shift[c4 + 1]) + r.y;
    o.z = gelu_tanh(v.z * g_scale[c4 + 2] + g_shift[c4 + 2]) + r.z;
    o.w = gelu_tanh(v.w * g_scale[c4 + 3] + g_shift[c4 + 3]) + r.w;
    if (MODE == 0) {
        ((float4*)hout)[idx] = o;
    } else {
        bf16 h0, l0, h1, l1, h2, l2, h3, l3;
        bsplit(o.x, h0, l0); bsplit(o.y, h1, l1);
        bsplit(o.z, h2, l2); bsplit(o.w, h3, l3);
        ((bf162*)oh)[idx * 2 + 0] = bf162{h0, h1};
        ((bf162*)oh)[idx * 2 + 1] = bf162{h2, h3};
        ((bf162*)ol)[idx * 2 + 0] = bf162{l0, l1};
        ((bf162*)ol)[idx * 2 + 1] = bf162{l2, l3};
    }
}

// ---------------- launch -----------------------------------------------------
extern "C" void kernel_launch(void* const* d_in, const int* in_sizes, int n_in,
                              void* d_out, int out_size) {
    const float* x = (const float*)d_in[0];
    const int* ei = (const int*)d_in[1];
    const int* mask = (const int*)d_in[2];
    const float* conv_w0 = (const float*)d_in[3];
    const float* conv_b0 = (const float*)d_in[4];
    const float* conv_w1 = (const float*)d_in[5];
    const float* conv_b1 = (const float*)d_in[6];
    const float* conv_w2 = (const float*)d_in[7];
    const float* conv_b2 = (const float*)d_in[8];
    const float* bn_g0 = (const float*)d_in[9];
    const float* bn_b0 = (const float*)d_in[10];
    const float* bn_g1 = (const float*)d_in[11];
    const float* bn_b1 = (const float*)d_in[12];
    const float* bn_g2 = (const float*)d_in[13];
    const float* bn_b2 = (const float*)d_in[14];
    const float* proj_w = (const float*)d_in[15];
    const float* proj_b = (const float*)d_in[16];
    const float* lin_w0 = (const float*)d_in[17];
    const float* lin_b0 = (const float*)d_in[18];
    const float* lin_w1 = (const float*)d_in[19];
    const float* lin_b1 = (const float*)d_in[20];
    const float* head_w = (const float*)d_in[21];
    const float* head_b = (const float*)d_in[22];
    float* out = (float*)d_out;

    const int* src = ei;
    const int* dst = ei + EE;

    float *p_h, *p_m, *p_res;
    bf16 *p1h, *p1l, *p2h, *p2l, *wh, *wl;
    cudaGetSymbolAddress((void**)&p_h, g_h);
    cudaGetSymbolAddress((void**)&p_m, g_m);
    cudaGetSymbolAddress((void**)&p_res, g_res);
    cudaGetSymbolAddress((void**)&p1h, g_p1h);
    cudaGetSymbolAddress((void**)&p1l, g_p1l);
    cudaGetSymbolAddress((void**)&p2h, g_p2h);
    cudaGetSymbolAddress((void**)&p2l, g_p2l);
    cudaGetSymbolAddress((void**)&wh, g_wh);
    cudaGetSymbolAddress((void**)&wl, g_wl);

    cudaFuncSetAttribute(k_bgemm<DIN, false, false, false, false>, cudaFuncAttributeMaxDynamicSharedMemorySize, (int)TGB_SMEM);
    cudaFuncSetAttribute(k_bgemm<DIN, false, true, false, false>, cudaFuncAttributeMaxDynamicSharedMemorySize, (int)TGB_SMEM);
    cudaFuncSetAttribute(k_bgemm<DH, false, true, false, false>, cudaFuncAttributeMaxDynamicSharedMemorySize, (int)TGB_SMEM);
    cudaFuncSetAttribute(k_bgemm<DH, true, false, true, false>, cudaFuncAttributeMaxDynamicSharedMemorySize, (int)TGB_SMEM);
    cudaFuncSetAttribute(k_bgemm<DH, true, false, false, true>, cudaFuncAttributeMaxDynamicSharedMemorySize, (int)TGB_SMEM);

    const int T = 256;
    const int WSTRIDE = DH * DH;
    dim3 tg_grid((NN + 127) / 128, 2);  // 391 x 2
    int ew4_256 = NN * (DH / 4);
    int gather_blocks = (NN * 32 + T - 1) / T;

    // ---- fork a side stream (host objects only) ----
    cudaStream_t s1;
    cudaEvent_t e0, e1;
    cudaStreamCreateWithFlags(&s1, cudaStreamNonBlocking);
    cudaEventCreateWithFlags(&e0, cudaEventDisableTiming);
    cudaEventCreateWithFlags(&e1, cudaEventDisableTiming);

    cudaEventRecord(e0, 0);
    cudaStreamWaitEvent(s1, e0, 0);

    // side stream: CSR build + degrees + layer-0 gather + stats zero + out zero
    k_zero_cnt<<<(NN + T - 1) / T, T, 0, s1>>>();
    k_deg_count<<<(EE + T - 1) / T, T, 0, s1>>>(dst);
    k_deg_final<<<(NN + T - 1) / T, T, 0, s1>>>();
    k_scan1<<<SCAN_B, 1024, 0, s1>>>();
    k_scan2<<<1, 64, 0, s1>>>();
    k_scan3<<<SCAN_B, 1024, 0, s1>>>();
    k_csr_fill<<<(EE + T - 1) / T, T, 0, s1>>>(src, dst);
    k_gather<DIN><<<gather_blocks, T, 0, s1>>>(x, p2h, p2l);
    k_zero_stats<<<2, T, 0, s1>>>();
    k_zero_out<<<(NN + T - 1) / T, T, 0, s1>>>(out);
    cudaEventRecord(e1, s1);

    // main stream: splits + proj GEMM (independent of CSR)
    k_split_x<<<(NN * DIN / 4 + T - 1) / T, T>>>(x, p1h, p1l);
    k_split_w<<<(DIN * DH + T - 1) / T, T>>>(proj_w, DIN, wh + 0 * WSTRIDE, wl + 0 * WSTRIDE);
    k_split_w<<<(DIN * DH + T - 1) / T, T>>>(conv_w0, DIN, wh + 1 * WSTRIDE, wl + 1 * WSTRIDE);
    k_split_w<<<(DH * DH + T - 1) / T, T>>>(conv_w1, DH, wh + 2 * WSTRIDE, wl + 2 * WSTRIDE);
    k_split_w<<<(DH * DH + T - 1) / T, T>>>(conv_w2, DH, wh + 3 * WSTRIDE, wl + 3 * WSTRIDE);
    k_split_w<<<(DH * DH + T - 1) / T, T>>>(lin_w0, DH, wh + 4 * WSTRIDE, wl + 4 * WSTRIDE);
    k_split_w<<<(DH * DH + T - 1) / T, T>>>(lin_w1, DH, wh + 5 * WSTRIDE, wl + 5 * WSTRIDE);
    k_bgemm<DIN, false, false, false, false><<<tg_grid, T, TGB_SMEM>>>(
        p1h, p1l, wh + 0 * WSTRIDE, wl + 0 * WSTRIDE, proj_b, p_res, nullptr, nullptr,
        nullptr, nullptr, NN);

    // join
    cudaStreamWaitEvent(0, e1, 0);

    // ---- GCN layer 0 ----
    k_bgemm<DIN, false, true, false, false><<<tg_grid, T, TGB_SMEM>>>(
        p2h, p2l, wh + 1 * WSTRIDE, wl + 1 * WSTRIDE, conv_b0, p_m, nullptr, nullptr,
        nullptr, nullptr, NN);
    k_bn_final<<<1, T>>>(bn_g0, bn_b0);
    k_bn_apply<0><<<(ew4_256 + T - 1) / T, T>>>(p_m, p_res, p_h, nullptr, nullptr);
    k_zero_stats<<<2, T>>>();

    // ---- GCN layer 1 ----
    k_gather<DH><<<gather_blocks, T>>>(p_h, p2h, p2l);
    k_bgemm<DH, false, true, false, false><<<tg_grid, T, TGB_SMEM>>>(
        p2h, p2l, wh + 2 * WSTRIDE, wl + 2 * WSTRIDE, conv_b1, p_m, nullptr, nullptr,
        nullptr, nullptr, NN);
    k_bn_final<<<1, T>>>(bn_g1, bn_b1);
    k_bn_apply<0><<<(ew4_256 + T - 1) / T, T>>>(p_m, p_h, p_h, nullptr, nullptr);
    k_zero_stats<<<2, T>>>();

    // ---- GCN layer 2 ----
    k_gather<DH><<<gather_blocks, T>>>(p_h, p2h, p2l);
    k_bgemm<DH, false, true, false, false><<<tg_grid, T, TGB_SMEM>>>(
        p2h, p2l, wh + 3 * WSTRIDE, wl + 3 * WSTRIDE, conv_b2, p_m, nullptr, nullptr,
        nullptr, nullptr, NN);
    k_bn_final<<<1, T>>>(bn_g2, bn_b2);
    k_bn_apply<1><<<(ew4_256 + T - 1) / T, T>>>(p_m, p_h, nullptr, p1h, p1l);

    // ---- MLP + fused head ----
    k_bgemm<DH, true, false, true, false><<<tg_grid, T, TGB_SMEM>>>(
        p1h, p1l, wh + 4 * WSTRIDE, wl + 4 * WSTRIDE, lin_b0, nullptr, p2h, p2l,
        nullptr, nullptr, NN);
    k_bgemm<DH, true, false, false, true><<<tg_grid, T, TGB_SMEM>>>(
        p2h, p2l, wh + 5 * WSTRIDE, wl + 5 * WSTRIDE, lin_b1, nullptr, nullptr, nullptr,
        head_w, out, NN);

    // ---- mask + bias ----
    k_mask_out<<<(NN + T - 1) / T, T>>>(out, mask, head_b);
}

// round 17
// speedup vs baseline: 1.5380x; 1.0945x over previous
#include <cuda_runtime.h>
#include <cuda_bf16.h>
#include <math.h>
#include <stdint.h>

#define NN 50000
#define EE 800000
#define DIN 128
#define DH 256
#define SCAN_B 49  // ceil(NN/1024)

typedef __nv_bfloat16 bf16;
typedef __nv_bfloat162 bf162;

// ---------------- scratch (static device globals; no allocations) -----------
__device__ __align__(16) float g_h[NN * DH];
__device__ __align__(16) float g_m[NN * DH];
__device__ __align__(16) float g_res[NN * DH];
__device__ __align__(16) bf16  g_p1h[NN * DH];
__device__ __align__(16) bf16  g_p1l[NN * DH];
__device__ __align__(16) bf16  g_p2h[NN * DH];
__device__ __align__(16) bf16  g_p2l[NN * DH];
__device__ __align__(16) bf16  g_wh[6 * DH * DH];  // transposed [N][K] hi planes
__device__ __align__(16) bf16  g_wl[6 * DH * DH];
__device__ __align__(16) int   g_cnt[NN];
__device__ __align__(16) int   g_off[NN + 1];
__device__ __align__(16) int   g_cursor[NN];
__device__ __align__(16) int   g_csr[EE];
__device__ __align__(16) int   g_bsum[64];
__device__ __align__(16) int   g_bbase[64];
__device__ __align__(16) float g_isd[NN];
__device__ __align__(16) float g_id[NN];
__device__ __align__(16) double g_stats[2 * DH];
__device__ __align__(16) float g_scale[DH];
__device__ __align__(16) float g_shift[DH];

// ---------------- helpers ---------------------------------------------------
__device__ __forceinline__ float gelu_tanh(float x) {
    float x3 = x * x * x;
    return 0.5f * x * (1.0f + tanhf(0.7978845608028654f * (x + 0.044715f * x3)));
}

__device__ __forceinline__ void bsplit(float x, bf16& h, bf16& l) {
    h = __float2bfloat16_rn(x);
    l = __float2bfloat16_rn(x - __bfloat162float(h));
}

__device__ __forceinline__ uint32_t smem_u32(const void* p) {
    uint32_t a;
    asm("{ .reg .u64 t; cvta.to.shared.u64 t, %1; cvt.u32.u64 %0, t; }" : "=r"(a) : "l"(p));
    return a;
}

__device__ __forceinline__ void mma_bf16(float& c0, float& c1, float& c2, float& c3,
                                         unsigned a0, unsigned a1, unsigned a2, unsigned a3,
                                         unsigned b0, unsigned b1) {
    asm volatile("mma.sync.aligned.m16n8k16.row.col.f32.bf16.bf16.f32 "
                 "{%0,%1,%2,%3},{%4,%5,%6,%7},{%8,%9},{%0,%1,%2,%3};"
                 : "+f"(c0), "+f"(c1), "+f"(c2), "+f"(c3)
                 : "r"(a0), "r"(a1), "r"(a2), "r"(a3), "r"(b0), "r"(b1));
}

__device__ __forceinline__ void cpa16(uint32_t d, const void* s, int srcsz) {
    asm volatile("cp.async.ca.shared.global [%0], [%1], 16, %2;"
                 :: "r"(d), "l"(s), "r"(srcsz) : "memory");
}

#define LDSM4(r0, r1, r2, r3, addr)                                            \
    asm volatile("ldmatrix.sync.aligned.m8n8.x4.shared.b16 {%0,%1,%2,%3}, [%4];" \
                 : "=r"(r0), "=r"(r1), "=r"(r2), "=r"(r3) : "r"(addr))
#define LDSM2(r0, r1, addr)                                                    \
    asm volatile("ldmatrix.sync.aligned.m8n8.x2.shared.b16 {%0,%1}, [%2];"     \
                 : "=r"(r0), "=r"(r1) : "r"(addr))

// ---------------- degree + CSR ----------------------------------------------
__global__ void k_zero_cnt() {
    int i = blockIdx.x * blockDim.x + threadIdx.x;
    if (i < NN) g_cnt[i] = 0;
}

__global__ void k_deg_count(const int* __restrict__ dst) {
    int e = blockIdx.x * blockDim.x + threadIdx.x;
    if (e < EE) atomicAdd(&g_cnt[dst[e]], 1);
}

__global__ void k_deg_final() {
    int i = blockIdx.x * blockDim.x + threadIdx.x;
    if (i < NN) {
        float d = (float)g_cnt[i] + 1.0f;
        g_isd[i] = rsqrtf(d);
        g_id[i] = 1.0f / d;
    }
}

__global__ void k_scan1() {
    __shared__ int sm[1024];
    int tid = threadIdx.x;
    int i = blockIdx.x * 1024 + tid;
    int v = (i < NN) ? g_cnt[i] : 0;
    sm[tid] = v;
    __syncthreads();
#pragma unroll
    for (int off = 1; off < 1024; off <<= 1) {
        int t = (tid >= off) ? sm[tid - off] : 0;
        __syncthreads();
        sm[tid] += t;
        __syncthreads();
    }
    if (i < NN) g_off[i + 1] = sm[tid];
    if (tid == 1023) g_bsum[blockIdx.x] = sm[1023];
}

__global__ void k_scan2() {
    __shared__ int sm[64];
    int tid = threadIdx.x;
    int v = (tid < SCAN_B) ? g_bsum[tid] : 0;
    sm[tid] = v;
    __syncthreads();
#pragma unroll
    for (int off = 1; off < 64; off <<= 1) {
        int t = (tid >= off) ? sm[tid - off] : 0;
        __syncthreads();
        sm[tid] += t;
        __syncthreads();
    }
    if (tid < SCAN_B) g_bbase[tid] = sm[tid] - v;
}

__global__ void k_scan3() {
    int i = blockIdx.x * 1024 + threadIdx.x;
    if (i < NN) {
        int incl = g_off[i + 1] + g_bbase[blockIdx.x];
        g_off[i + 1] = incl;
        g_cursor[i] = incl - g_cnt[i];
    }
    if (i == 0) g_off[0] = 0;
}

__global__ void k_csr_fill(const int* __restrict__ src, const int* __restrict__ dst) {
    int e = blockIdx.x * blockDim.x + threadIdx.x;
    if (e < EE) {
        int p = atomicAdd(&g_cursor[dst[e]], 1);
        g_csr[p] = src[e];
    }
}

// ---------------- splitting producers ---------------------------------------
__global__ void k_split_x(const float* __restrict__ x, bf16* __restrict__ oh,
                          bf16* __restrict__ ol) {
    int idx = blockIdx.x * blockDim.x + threadIdx.x;  // float4 index
    if (idx >= NN * (DIN / 4)) return;
    float4 v = ((const float4*)x)[idx];
    bf16 h0, l0, h1, l1, h2, l2, h3, l3;
    bsplit(v.x, h0, l0); bsplit(v.y, h1, l1);
    bsplit(v.z, h2, l2); bsplit(v.w, h3, l3);
    ((bf162*)oh)[idx * 2 + 0] = bf162{h0, h1};
    ((bf162*)oh)[idx * 2 + 1] = bf162{h2, h3};
    ((bf162*)ol)[idx * 2 + 0] = bf162{l0, l1};
    ((bf162*)ol)[idx * 2 + 1] = bf162{l2, l3};
}

__global__ void k_split_w(const float* __restrict__ W, int K,
                          bf16* __restrict__ oh, bf16* __restrict__ ol) {
    int idx = blockIdx.x * blockDim.x + threadIdx.x;
    if (idx >= K * DH) return;
    int k = idx / DH, n = idx % DH;
    bf16 h, l;
    bsplit(W[idx], h, l);
    oh[n * K + k] = h;
    ol[n * K + k] = l;
}

__global__ void k_zero_out(float* __restrict__ out) {
    int i = blockIdx.x * blockDim.x + threadIdx.x;
    if (i < NN) out[i] = 0.0f;
}

__global__ void k_mask_out(float* __restrict__ out, const int* __restrict__ mask,
                           const float* __restrict__ hb) {
    int i = blockIdx.x * blockDim.x + threadIdx.x;
    if (i < NN) out[i] = (mask[i] != 0) ? (out[i] + __ldg(&hb[0])) : 0.0f;
}

// ---------------- aggregation: warp-per-node CSR gather -> planes -----------
template <int D>
__global__ void k_gather(const float* __restrict__ h, bf16* __restrict__ oh,
                         bf16* __restrict__ ol) {
    int w = (blockIdx.x * blockDim.x + threadIdx.x) >> 5;
    int lane = threadIdx.x & 31;
    if (w >= NN) return;
    const int NF = D / 128;
    const float4* hn = (const float4*)(h + (size_t)w * D);
    float idg = g_id[w], isdd = g_isd[w];
    float4 acc[NF];
#pragma unroll
    for (int t = 0; t < NF; t++) {
        float4 v = hn[lane + 32 * t];
        acc[t] = make_float4(v.x * idg, v.y * idg, v.z * idg, v.w * idg);
    }
    int e0 = g_off[w], e1 = g_off[w + 1];
    int e = e0;
#pragma unroll 1
    for (; e + 2 <= e1; e += 2) {
        int s0 = __ldg(&g_csr[e]);
        int s1 = __ldg(&g_csr[e + 1]);
        float c0 = isdd * __ldg(&g_isd[s0]);
        float c1 = isdd * __ldg(&g_isd[s1]);
        const float4* h0 = (const float4*)(h + (size_t)s0 * D);
        const float4* h1 = (const float4*)(h + (size_t)s1 * D);
#pragma unroll
        for (int t = 0; t < NF; t++) {
            float4 v0 = __ldg(&h0[lane + 32 * t]);
            float4 v1 = __ldg(&h1[lane + 32 * t]);
            acc[t].x += c0 * v0.x + c1 * v1.x;
            acc[t].y += c0 * v0.y + c1 * v1.y;
            acc[t].z += c0 * v0.z + c1 * v1.z;
            acc[t].w += c0 * v0.w + c1 * v1.w;
        }
    }
    if (e < e1) {
        int s0 = __ldg(&g_csr[e]);
        float c0 = isdd * __ldg(&g_isd[s0]);
        const float4* h0 = (const float4*)(h + (size_t)s0 * D);
#pragma unroll
        for (int t = 0; t < NF; t++) {
            float4 v0 = __ldg(&h0[lane + 32 * t]);
            acc[t].x += c0 * v0.x; acc[t].y += c0 * v0.y;
            acc[t].z += c0 * v0.z; acc[t].w += c0 * v0.w;
        }
    }
#pragma unroll
    for (int t = 0; t < NF; t++) {
        int i4 = w * (D / 4) + lane + 32 * t;
        bf16 h0, l0, h1, l1, h2, l2, h3, l3;
        bsplit(acc[t].x, h0, l0); bsplit(acc[t].y, h1, l1);
        bsplit(acc[t].z, h2, l2); bsplit(acc[t].w, h3, l3);
        ((bf162*)oh)[i4 * 2 + 0] = bf162{h0, h1};
        ((bf162*)oh)[i4 * 2 + 1] = bf162{h2, h3};
        ((bf162*)ol)[i4 * 2 + 0] = bf162{l0, l1};
        ((bf162*)ol)[i4 * 2 + 1] = bf162{l2, l3};
    }
}

// ---------------- bf16x2 tensor-core GEMM (cp.async + ldmatrix, BK=32) ------
// C[M x 256] = (Ah+Al)[M x K] @ (Bh+Bl)^T   (B planes are [N][K])
// block 128(M) x 128(N), BK=32, 256 threads = 8 warps, warp tile 64x32.
// XOR-swizzled 64B rows: physical chunk = logical ^ ((row>>1)&3).
// 3-stage ring, one barrier + one wait per iteration.
#define PLB 8192                    // plane bytes: 128 rows x 64B
#define STB 32768                   // stage bytes: 4 planes
#define NSTAGE 3
#define TGB_SMEM (size_t)(NSTAGE * STB)  // 98304 B

template <int K, bool GELU, bool STATS, bool PLANES, bool HEAD>
__global__ void __launch_bounds__(256, 2) k_bgemm(
        const bf16* __restrict__ Ah, const bf16* __restrict__ Al,
        const bf16* __restrict__ BhT, const bf16* __restrict__ BlT,
        const float* __restrict__ bias, float* __restrict__ C,
        bf16* __restrict__ Ch, bf16* __restrict__ Cl,
        const float* __restrict__ headw, float* __restrict__ outv, int M) {
    const int BK = 32, NC = K / BK;
    extern __shared__ bf16 smp[];

    int bm = blockIdx.x * 128;
    int bn = blockIdx.y * 128;
    int tid = threadIdx.x;
    int wid = tid >> 5, lane = tid & 31;
    int g = lane >> 2, t = lane & 3;
    int warp_m = (wid & 1) * 64;
    int warp_n = (wid >> 1) * 32;

    // cp.async mapping: row = tid/2, logical chunk pair = (tid&1)*2
    int crow = tid >> 1;
    int cpair = (tid & 1) * 2;
    int vst = (crow >> 1) & 3;
    bool arowok = (bm + crow) < M;
    const bf16* gA_h = Ah + (size_t)(arowok ? bm + crow : 0) * K + cpair * 8;
    const bf16* gA_l = Al + (size_t)(arowok ? bm + crow : 0) * K + cpair * 8;
    const bf16* gB_h = BhT + (size_t)(bn + crow) * K + cpair * 8;
    const bf16* gB_l = BlT + (size_t)(bn + crow) * K + cpair * 8;
    int asz = arowok ? 16 : 0;
    uint32_t smbase = smem_u32(smp);
    uint32_t d0 = smbase + (uint32_t)(crow * 64 + (((cpair + 0) ^ vst) << 4));
    uint32_t d1 = smbase + (uint32_t)(crow * 64 + (((cpair + 1) ^ vst) << 4));

    // ldmatrix lane mapping (rows/fragments identical to padded version)
    int l8 = lane & 7, lh = (lane >> 3) & 1, lq = lane >> 4;
    int rowAl = l8 + lh * 8;                 // local row within 16-row group
    int vA = (rowAl >> 1) & 3;
    uint32_t baseA = (uint32_t)((warp_m + rowAl) * 64);
    int vB = (l8 >> 1) & 3;
    uint32_t baseB = (uint32_t)((warp_n + l8) * 64);
    uint32_t aoff[2], boff[2];
#pragma unroll
    for (int ks = 0; ks < 2; ks++) {
        aoff[ks] = baseA + (uint32_t)((((2 * ks + lq) ^ vA)) << 4);
        boff[ks] = baseB + (uint32_t)((((2 * ks + lh) ^ vB)) << 4);
    }

    float acc[4][4][4];
#pragma unroll
    for (int m = 0; m < 4; m++)
#pragma unroll
        for (int n = 0; n < 4; n++)
#pragma unroll
            for (int c = 0; c < 4; c++) acc[m][n][c] = 0.f;

#define ISSUE(s)                                                  \
    do {                                                          \
        uint32_t bb = (uint32_t)(((s) % NSTAGE) * STB);           \
        int k0_ = (s) * BK;                                       \
        cpa16(d0 + bb, gA_h + k0_, asz);                          \
        cpa16(d1 + bb, gA_h + k0_ + 8, asz);                      \
        cpa16(d0 + bb + PLB, gA_l + k0_, asz);                    \
        cpa16(d1 + bb + PLB, gA_l + k0_ + 8, asz);                \
        cpa16(d0 + bb + 2 * PLB, gB_h + k0_, 16);                 \
        cpa16(d1 + bb + 2 * PLB, gB_h + k0_ + 8, 16);             \
        cpa16(d0 + bb + 3 * PLB, gB_l + k0_, 16);                 \
        cpa16(d1 + bb + 3 * PLB, gB_l + k0_ + 8, 16);             \
        asm volatile("cp.async.commit_group;" ::: "memory");      \
    } while (0)

    ISSUE(0); ISSUE(1);

#pragma unroll 1
    for (int c = 0; c < NC; c++) {
        if (c + 1 < NC) {
            asm volatile("cp.async.wait_group 1;" ::: "memory");
        } else {
            asm volatile("cp.async.wait_group 0;" ::: "memory");
        }
        __syncthreads();  // single barrier per iteration (3-stage ring)
        if (c + 2 < NC) ISSUE(c + 2);  // stage (c-1)%3: all warps done at prev barrier

        uint32_t st = smbase + (uint32_t)((c % NSTAGE) * STB);
#pragma unroll
        for (int ks = 0; ks < 2; ks++) {
            unsigned bH[4][2], bL[4][2];
#pragma unroll
            for (int n = 0; n < 4; n++) {
                uint32_t ad = st + 2 * PLB + boff[ks] + (uint32_t)(n * 512);
                LDSM2(bH[n][0], bH[n][1], ad);
                LDSM2(bL[n][0], bL[n][1], ad + PLB);
            }
#pragma unroll
            for (int m = 0; m < 4; m++) {
                uint32_t ad = st + aoff[ks] + (uint32_t)(m * 1024);
                unsigned aH0, aH1, aH2, aH3, aL0, aL1, aL2, aL3;
                LDSM4(aH0, aH1, aH2, aH3, ad);
                LDSM4(aL0, aL1, aL2, aL3, ad + PLB);
#pragma unroll
                for (int n = 0; n < 4; n++) {
                    float* cc = acc[m][n];
                    mma_bf16(cc[0], cc[1], cc[2], cc[3],
                             aH0, aH1, aH2, aH3, bL[n][0], bL[n][1]);
                    mma_bf16(cc[0], cc[1], cc[2], cc[3],
                             aL0, aL1, aL2, aL3, bH[n][0], bH[n][1]);
                    mma_bf16(cc[0], cc[1], cc[2], cc[3],
                             aH0, aH1, aH2, aH3, bH[n][0], bH[n][1]);
                }
            }
        }
    }
#undef ISSUE

    // ---- epilogue ----
    float s_sum[4][2], s_sq[4][2];
    if (STATS) {
#pragma unroll
        for (int n = 0; n < 4; n++)
#pragma unroll
            for (int p = 0; p < 2; p++) { s_sum[n][p] = 0.f; s_sq[n][p] = 0.f; }
    }
    float rsum[4][2];
    if (HEAD) {
#pragma unroll
        for (int m = 0; m < 4; m++) { rsum[m][0] = 0.f; rsum[m][1] = 0.f; }
    }
#pragma unroll
    for (int m = 0; m < 4; m++) {
        int row0 = bm + warp_m + m * 16;
#pragma unroll
        for (int n = 0; n < 4; n++) {
            int col = bn + warp_n + n * 8 + t * 2;
            float b0 = __ldg(&bias[col]), b1 = __ldg(&bias[col + 1]);
            float w0, w1;
            if (HEAD) { w0 = __ldg(&headw[col]); w1 = __ldg(&headw[col + 1]); }
#pragma unroll
            for (int half = 0; half < 2; half++) {
                int r = row0 + g + half * 8;
                if (r >= M) continue;
                float2 o = make_float2(acc[m][n][half * 2 + 0] + b0,
                                       acc[m][n][half * 2 + 1] + b1);
                if (STATS) {
                    s_sum[n][0] += o.x; s_sq[n][0] += o.x * o.x;
                    s_sum[n][1] += o.y; s_sq[n][1] += o.y * o.y;
                }
                if (GELU) { o.x = gelu_tanh(o.x); o.y = gelu_tanh(o.y); }
                if (HEAD) {
                    rsum[m][half] += o.x * w0 + o.y * w1;
                } else if (PLANES) {
                    bf16 h0, l0, h1, l1;
                    bsplit(o.x, h0, l0); bsplit(o.y, h1, l1);
                    *(bf162*)(Ch + (size_t)r * DH + col) = bf162{h0, h1};
                    *(bf162*)(Cl + (size_t)r * DH + col) = bf162{l0, l1};
                } else {
                    *(float2*)(C + (size_t)r * DH + col) = o;
                }
            }
        }
    }
    if (HEAD) {
#pragma unroll
        for (int m = 0; m < 4; m++)
#pragma unroll
            for (int half = 0; half < 2; half++) {
                float v = rsum[m][half];
                v += __shfl_xor_sync(0xffffffffu, v, 1);
                v += __shfl_xor_sync(0xffffffffu, v, 2);
                int r = bm + warp_m + m * 16 + g + half * 8;
                if (t == 0 && r < M) atomicAdd(&outv[r], v);
            }
    }
    if (STATS) {
#pragma unroll
        for (int n = 0; n < 4; n++)
#pragma unroll
            for (int p = 0; p < 2; p++) {
#pragma unroll
                for (int off = 4; off < 32; off <<= 1) {
                    s_sum[n][p] += __shfl_xor_sync(0xffffffffu, s_sum[n][p], off);
                    s_sq[n][p] += __shfl_xor_sync(0xffffffffu, s_sq[n][p], off);
                }
            }
        if (lane < 4) {
#pragma unroll
            for (int n = 0; n < 4; n++)
#pragma unroll
                for (int p = 0; p < 2; p++) {
                    int col = bn + warp_n + n * 8 + lane * 2 + p;
                    atomicAdd(&g_stats[col], (double)s_sum[n][p]);
                    atomicAdd(&g_stats[DH + col], (double)s_sq[n][p]);
                }
        }
    }
}

// ---------------- batchnorm -------------------------------------------------
__global__ void k_zero_stats() {
    int i = blockIdx.x * blockDim.x + threadIdx.x;
    if (i < 2 * DH) g_stats[i] = 0.0;
}

__global__ void k_bn_final(const float* __restrict__ gamma, const float* __restrict__ beta) {
    int c = threadIdx.x;
    double mean = g_stats[c] / (double)NN;
    double var = g_stats[DH + c] / (double)NN - mean * mean;
    double sc = (double)gamma[c] / sqrt(var + 1e-5);
    g_scale[c] = (float)sc;
    g_shift[c] = (float)((double)beta[c] - mean * sc);
}

// MODE 0: fp32 out; MODE 1: bf16 planes out only
template <int MODE>
__global__ void k_bn_apply(const float* __restrict__ m, const float* __restrict__ res,
                           float* __restrict__ hout, bf16* __restrict__ oh,
                           bf16* __restrict__ ol) {
    int idx = blockIdx.x * blockDim.x + threadIdx.x;  // float4 index
    if (idx >= NN * (DH / 4)) return;
    int c4 = (idx & (DH / 4 - 1)) * 4;
    float4 v = ((const float4*)m)[idx];
    float4 r = ((const float4*)res)[idx];
    float4 o;
    o.x = gelu_tanh(v.x * g_scale[c4 + 0] + g_shift[c4 + 0]) + r.x;
    o.y = gelu_tanh(v.y * g_scale[c4 + 1] + g_shift[c4 + 1]) + r.y;
    o.z = gelu_tanh(v.z * g_scale[c4 + 2] + g_shift[c4 + 2]) + r.z;
    o.w = gelu_tanh(v.w * g_scale[c4 + 3] + g_shift[c4 + 3]) + r.w;
    if (MODE == 0) {
        ((float4*)hout)[idx] = o;
    } else {
        bf16 h0, l0, h1, l1, h2, l2, h3, l3;
        bsplit(o.x, h0, l0); bsplit(o.y, h1, l1);
        bsplit(o.z, h2, l2); bsplit(o.w, h3, l3);
        ((bf162*)oh)[idx * 2 + 0] = bf162{h0, h1};
        ((bf162*)oh)[idx * 2 + 1] = bf162{h2, h3};
        ((bf162*)ol)[idx * 2 + 0] = bf162{l0, l1};
        ((bf162*)ol)[idx * 2 + 1] = bf162{l2, l3};
    }
}

// ---------------- launch -----------------------------------------------------
extern "C" void kernel_launch(void* const* d_in, const int* in_sizes, int n_in,
                              void* d_out, int out_size) {
    const float* x = (const float*)d_in[0];
    const int* ei = (const int*)d_in[1];
    const int* mask = (const int*)d_in[2];
    const float* conv_w0 = (const float*)d_in[3];
    const float* conv_b0 = (const float*)d_in[4];
    const float* conv_w1 = (const float*)d_in[5];
    const float* conv_b1 = (const float*)d_in[6];
    const float* conv_w2 = (const float*)d_in[7];
    const float* conv_b2 = (const float*)d_in[8];
    const float* bn_g0 = (const float*)d_in[9];
    const float* bn_b0 = (const float*)d_in[10];
    const float* bn_g1 = (const float*)d_in[11];
    const float* bn_b1 = (const float*)d_in[12];
    const float* bn_g2 = (const float*)d_in[13];
    const float* bn_b2 = (const float*)d_in[14];
    const float* proj_w = (const float*)d_in[15];
    const float* proj_b = (const float*)d_in[16];
    const float* lin_w0 = (const float*)d_in[17];
    const float* lin_b0 = (const float*)d_in[18];
    const float* lin_w1 = (const float*)d_in[19];
    const float* lin_b1 = (const float*)d_in[20];
    const float* head_w = (const float*)d_in[21];
    const float* head_b = (const float*)d_in[22];
    float* out = (float*)d_out;

    const int* src = ei;
    const int* dst = ei + EE;

    float *p_h, *p_m, *p_res;
    bf16 *p1h, *p1l, *p2h, *p2l, *wh, *wl;
    cudaGetSymbolAddress((void**)&p_h, g_h);
    cudaGetSymbolAddress((void**)&p_m, g_m);
    cudaGetSymbolAddress((void**)&p_res, g_res);
    cudaGetSymbolAddress((void**)&p1h, g_p1h);
    cudaGetSymbolAddress((void**)&p1l, g_p1l);
    cudaGetSymbolAddress((void**)&p2h, g_p2h);
    cudaGetSymbolAddress((void**)&p2l, g_p2l);
    cudaGetSymbolAddress((void**)&wh, g_wh);
    cudaGetSymbolAddress((void**)&wl, g_wl);

    cudaFuncSetAttribute(k_bgemm<DIN, false, false, false, false>, cudaFuncAttributeMaxDynamicSharedMemorySize, (int)TGB_SMEM);
    cudaFuncSetAttribute(k_bgemm<DIN, false, true, false, false>, cudaFuncAttributeMaxDynamicSharedMemorySize, (int)TGB_SMEM);
    cudaFuncSetAttribute(k_bgemm<DH, false, true, false, false>, cudaFuncAttributeMaxDynamicSharedMemorySize, (int)TGB_SMEM);
    cudaFuncSetAttribute(k_bgemm<DH, true, false, true, false>, cudaFuncAttributeMaxDynamicSharedMemorySize, (int)TGB_SMEM);
    cudaFuncSetAttribute(k_bgemm<DH, true, false, false, true>, cudaFuncAttributeMaxDynamicSharedMemorySize, (int)TGB_SMEM);

    const int T = 256;
    const int WSTRIDE = DH * DH;
    dim3 tg_grid((NN + 127) / 128, 2);  // 391 x 2
    int ew4_256 = NN * (DH / 4);
    int gather_blocks = (NN * 32 + T - 1) / T;

    // ---- fork a side stream (host objects only) ----
    cudaStream_t s1;
    cudaEvent_t e0, e1;
    cudaStreamCreateWithFlags(&s1, cudaStreamNonBlocking);
    cudaEventCreateWithFlags(&e0, cudaEventDisableTiming);
    cudaEventCreateWithFlags(&e1, cudaEventDisableTiming);

    cudaEventRecord(e0, 0);
    cudaStreamWaitEvent(s1, e0, 0);

    // side stream: CSR build + degrees + layer-0 gather + stats zero + out zero
    k_zero_cnt<<<(NN + T - 1) / T, T, 0, s1>>>();
    k_deg_count<<<(EE + T - 1) / T, T, 0, s1>>>(dst);
    k_deg_final<<<(NN + T - 1) / T, T, 0, s1>>>();
    k_scan1<<<SCAN_B, 1024, 0, s1>>>();
    k_scan2<<<1, 64, 0, s1>>>();
    k_scan3<<<SCAN_B, 1024, 0, s1>>>();
    k_csr_fill<<<(EE + T - 1) / T, T, 0, s1>>>(src, dst);
    k_gather<DIN><<<gather_blocks, T, 0, s1>>>(x, p2h, p2l);
    k_zero_stats<<<2, T, 0, s1>>>();
    k_zero_out<<<(NN + T - 1) / T, T, 0, s1>>>(out);
    cudaEventRecord(e1, s1);

    // main stream: splits + proj GEMM (independent of CSR)
    k_split_x<<<(NN * DIN / 4 + T - 1) / T, T>>>(x, p1h, p1l);
    k_split_w<<<(DIN * DH + T - 1) / T, T>>>(proj_w, DIN, wh + 0 * WSTRIDE, wl + 0 * WSTRIDE);
    k_split_w<<<(DIN * DH + T - 1) / T, T>>>(conv_w0, DIN, wh + 1 * WSTRIDE, wl + 1 * WSTRIDE);
    k_split_w<<<(DH * DH + T - 1) / T, T>>>(conv_w1, DH, wh + 2 * WSTRIDE, wl + 2 * WSTRIDE);
    k_split_w<<<(DH * DH + T - 1) / T, T>>>(conv_w2, DH, wh + 3 * WSTRIDE, wl + 3 * WSTRIDE);
    k_split_w<<<(DH * DH + T - 1) / T, T>>>(lin_w0, DH, wh + 4 * WSTRIDE, wl + 4 * WSTRIDE);
    k_split_w<<<(DH * DH + T - 1) / T, T>>>(lin_w1, DH, wh + 5 * WSTRIDE, wl + 5 * WSTRIDE);
    k_bgemm<DIN, false, false, false, false><<<tg_grid, T, TGB_SMEM>>>(
        p1h, p1l, wh + 0 * WSTRIDE, wl + 0 * WSTRIDE, proj_b, p_res, nullptr, nullptr,
        nullptr, nullptr, NN);

    // join
    cudaStreamWaitEvent(0, e1, 0);

    // ---- GCN layer 0 ----
    k_bgemm<DIN, false, true, false, false><<<tg_grid, T, TGB_SMEM>>>(
        p2h, p2l, wh + 1 * WSTRIDE, wl + 1 * WSTRIDE, conv_b0, p_m, nullptr, nullptr,
        nullptr, nullptr, NN);
    k_bn_final<<<1, T>>>(bn_g0, bn_b0);
    k_bn_apply<0><<<(ew4_256 + T - 1) / T, T>>>(p_m, p_res, p_h, nullptr, nullptr);
    k_zero_stats<<<2, T>>>();

    // ---- GCN layer 1 ----
    k_gather<DH><<<gather_blocks, T>>>(p_h, p2h, p2l);
    k_bgemm<DH, false, true, false, false><<<tg_grid, T, TGB_SMEM>>>(
        p2h, p2l, wh + 2 * WSTRIDE, wl + 2 * WSTRIDE, conv_b1, p_m, nullptr, nullptr,
        nullptr, nullptr, NN);
    k_bn_final<<<1, T>>>(bn_g1, bn_b1);
    k_bn_apply<0><<<(ew4_256 + T - 1) / T, T>>>(p_m, p_h, p_h, nullptr, nullptr);
    k_zero_stats<<<2, T>>>();

    // ---- GCN layer 2 ----
    k_gather<DH><<<gather_blocks, T>>>(p_h, p2h, p2l);
    k_bgemm<DH, false, true, false, false><<<tg_grid, T, TGB_SMEM>>>(
        p2h, p2l, wh + 3 * WSTRIDE, wl + 3 * WSTRIDE, conv_b2, p_m, nullptr, nullptr,
        nullptr, nullptr, NN);
    k_bn_final<<<1, T>>>(bn_g2, bn_b2);
    k_bn_apply<1><<<(ew4_256 + T - 1) / T, T>>>(p_m, p_h, nullptr, p1h, p1l);

    // ---- MLP + fused head ----
    k_bgemm<DH, true, false, true, false><<<tg_grid, T, TGB_SMEM>>>(
        p1h, p1l, wh + 4 * WSTRIDE, wl + 4 * WSTRIDE, lin_b0, nullptr, p2h, p2l,
        nullptr, nullptr, NN);
    k_bgemm<DH, true, false, false, true><<<tg_grid, T, TGB_SMEM>>>(
        p2h, p2l, wh + 5 * WSTRIDE, wl + 5 * WSTRIDE, lin_b1, nullptr, nullptr, nullptr,
        head_w, out, NN);

    // ---- mask + bias ----
    k_mask_out<<<(NN + T - 1) / T, T>>>(out, mask, head_b);
}